// round 11
// baseline (speedup 1.0000x reference)
#include <cuda_runtime.h>
#include <cstdint>

// Shapes (fixed by the problem instance)
#define B_  4
#define H_  96
#define W_  96
#define D_  96
#define NWH 12            // 96/8
#define NUM_WIN 1728      // 12*12*12
#define LEN_KEEP 691      // int(1728*0.4)
#define ELEMS_PER_OUT (B_*H_*W_*D_*32)   // 113,246,208 floats

#define NWTOT (B_ * NUM_WIN)             // 6912 windows total
#define NPAIR (NWTOT / 2)                // 3456 window pairs
#define TOTAL_BLOCKS (2 * NPAIR)         // 6912: xm pairs + mk pairs

// ---------------------------------------------------------------------------
// Single fused kernel, no inter-block synchronization.
// Block bid < NPAIR : writes the x_masked stream of windows {2p, 2p+1}
//                     (kept -> copy x, masked -> zeros).
// Block bid >= NPAIR: writes the mask stream of windows {2p, 2p+1}
//                     (kept -> 0.0, masked -> 1.0).
// kept is decided in-block via the stable-argsort-equivalent rank:
//   rank_i = #{ j : noise_j < noise_i or (noise_j == noise_i and j < i) }
//   kept   = rank_i < LEN_KEEP
// Both windows of the pair share one pass over the batch's 1728 noise keys
// (each thread loads 4 values, compares against both keys, packs the two
// counts into one int), one warp shfl-reduce + ONE block barrier + local
// 16-way smem sum. Noise is L2-resident after wave 1 -> prologue ~0.3us,
// amortized over a 128 KB single-stream body.
// Window pairs never cross batches (1728 even). Each window = 64 segments
// of 1 KB (8 voxels along d x 32 channels); 8 float4 per thread per window.
// ---------------------------------------------------------------------------
__global__ void __launch_bounds__(512)
fused_kernel(const float4* __restrict__ x,
             float4* __restrict__ out_xm,
             float4* __restrict__ out_mk,
             const float* __restrict__ noise) {
    __shared__ int wred[16];

    const int bid    = blockIdx.x;
    const bool is_xm = (bid < NPAIR);
    const int p  = is_xm ? bid : bid - NPAIR;  // pair index
    const int g0 = 2 * p;                      // first global window id
    const int b  = g0 / NUM_WIN;
    const int i0 = g0 - b * NUM_WIN;           // window index within batch
    const int i1 = i0 + 1;

    const int tid  = threadIdx.x;
    const int lane = tid & 31;
    const int wid  = tid >> 5;

    // ---- ranks of windows i0, i1 within batch b (packed 16+16) ----
    const float* nb = noise + b * NUM_WIN;
    const unsigned int v0 = __float_as_uint(__ldg(&nb[i0]));
    const unsigned int v1 = __float_as_uint(__ldg(&nb[i1]));
    int cnt = 0;
#pragma unroll
    for (int k = 0; k < 4; k++) {
        const int j = tid + k * 512;
        if (j < NUM_WIN) {
            const unsigned int u = __float_as_uint(__ldg(&nb[j]));
            // raw-bit compare is exact: noise in [0,1), all positive floats
            cnt += ((u < v0) || (u == v0 && j < i0));
            cnt += ((u < v1) || (u == v1 && j < i1)) << 16;
        }
    }
#pragma unroll
    for (int o = 16; o > 0; o >>= 1)
        cnt += __shfl_xor_sync(0xFFFFFFFFu, cnt, o);
    if (lane == 0) wred[wid] = cnt;
    __syncthreads();
    int packed = 0;
#pragma unroll
    for (int k = 0; k < 16; k++) packed += wred[k];
    const bool kept0 = (packed & 0xFFFF) < LEN_KEEP;
    const bool kept1 = ((unsigned)packed >> 16) < LEN_KEEP;

    // ---- per-thread segment geometry (same for both windows) ----
    const int seg   = tid >> 3;        // 0..63 window segment
    const int lane8 = tid & 7;
    const int dh = seg >> 3;
    const int dw = seg & 7;

#pragma unroll
    for (int wsel = 0; wsel < 2; wsel++) {
        const int i    = wsel ? i1 : i0;
        const bool kept = wsel ? kept1 : kept0;

        const int wd3 = i % NWH;
        const int r2  = i / NWH;
        const int ww3 = r2 % NWH;
        const int wh3 = r2 / NWH;
        const int h = wh3 * 8 + dh;
        const int w = ww3 * 8 + dw;
        // float4 base of this segment (8 voxels along d, 32 ch = 64 float4)
        const int s0 = (((b * H_ + h) * W_ + w) * D_ + wd3 * 8) * 8 + lane8;

        if (is_xm) {
            if (kept) {
                float4 v[8];
#pragma unroll
                for (int k = 0; k < 8; k++)
                    v[k] = __ldcs(&x[s0 + k * 8]);
#pragma unroll
                for (int k = 0; k < 8; k++)
                    __stcs(&out_xm[s0 + k * 8], v[k]);
            } else {
                const float4 z = make_float4(0.f, 0.f, 0.f, 0.f);
#pragma unroll
                for (int k = 0; k < 8; k++)
                    __stcs(&out_xm[s0 + k * 8], z);
            }
        } else {
            const float fv = kept ? 0.0f : 1.0f;
            const float4 c = make_float4(fv, fv, fv, fv);
#pragma unroll
            for (int k = 0; k < 8; k++)
                __stcs(&out_mk[s0 + k * 8], c);
        }
    }
}

extern "C" void kernel_launch(void* const* d_in, const int* in_sizes, int n_in,
                              void* d_out, int out_size) {
    const float* x     = (const float*)d_in[0];   // [B,H,W,D,C] fp32
    const float* noise = (const float*)d_in[1];   // [B, 1728]   fp32
    float* out = (float*)d_out;                   // [x_masked | mask]

    fused_kernel<<<TOTAL_BLOCKS, 512>>>(
        (const float4*)x,
        (float4*)out,
        (float4*)(out + (long long)ELEMS_PER_OUT),
        noise);
}

// round 12
// speedup vs baseline: 1.0035x; 1.0035x over previous
#include <cuda_runtime.h>
#include <cstdint>

// Shapes (fixed by the problem instance)
#define B_  4
#define H_  96
#define W_  96
#define D_  96
#define NWH 12            // 96/8
#define NUM_WIN 1728      // 12*12*12
#define LEN_KEEP 691      // int(1728*0.4)
#define ELEMS_PER_OUT (B_*H_*W_*D_*32)   // 113,246,208 floats

#define NWTOT (B_ * NUM_WIN)             // 6912 windows total
#define NPAIR (NWTOT / 2)                // 3456 window pairs
#define TOTAL_BLOCKS (2 * NPAIR)         // 6912: xm pairs + mk pairs
#define NQUADS (NUM_WIN / 4)             // 432 float4s of noise per batch

// ---------------------------------------------------------------------------
// Single fused kernel, no inter-block synchronization.
// Block bid < NPAIR : writes the x_masked stream of windows {2p, 2p+1}
//                     (kept -> copy x, masked -> zeros).
// Block bid >= NPAIR: writes the mask stream of windows {2p, 2p+1}
//                     (kept -> 0.0, masked -> 1.0).
// kept is decided in-block via the stable-argsort-equivalent rank:
//   rank_i = #{ j : noise_j < noise_i or (noise_j == noise_i and j < i) }
//   kept   = rank_i < LEN_KEEP
// LSU-frugal prologue: the 1728-key scan is done with 432 LDG.128 (threads
// 0..431 load ONE float4 each and compare its 4 values against both window
// keys) instead of 2048 scalar loads — the LSU issue pipe is co-saturated
// with DRAM in this kernel, so memory-instruction COUNT is what matters.
// Counts for both windows packed 16+16 into one int; one warp shfl-reduce,
// ONE block barrier, 16-way smem sum.
// Each block writes exactly ONE output stream of TWO windows: per window,
// 64 segments of 1 KB (8 voxels along d x 32 channels), 8 float4/thread.
// ---------------------------------------------------------------------------
__global__ void __launch_bounds__(512)
fused_kernel(const float4* __restrict__ x,
             float4* __restrict__ out_xm,
             float4* __restrict__ out_mk,
             const float* __restrict__ noise) {
    __shared__ int wred[16];

    const int bid    = blockIdx.x;
    const bool is_xm = (bid < NPAIR);
    const int p  = is_xm ? bid : bid - NPAIR;  // pair index
    const int g0 = 2 * p;                      // first global window id
    const int b  = g0 / NUM_WIN;
    const int i0 = g0 - b * NUM_WIN;           // window index within batch
    const int i1 = i0 + 1;

    const int tid  = threadIdx.x;
    const int lane = tid & 31;
    const int wid  = tid >> 5;

    // ---- ranks of windows i0, i1 within batch b (packed 16+16) ----
    const float*  nb  = noise + b * NUM_WIN;
    const float4* nb4 = (const float4*)nb;     // b*1728 floats: 16B aligned
    const unsigned int v0 = __float_as_uint(__ldg(&nb[i0]));
    const unsigned int v1 = __float_as_uint(__ldg(&nb[i1]));

    int cnt = 0;
    if (tid < NQUADS) {
        const float4 q = __ldg(&nb4[tid]);     // ONE vector load per thread
        const int j0 = 4 * tid;
        const unsigned int u0 = __float_as_uint(q.x);
        const unsigned int u1 = __float_as_uint(q.y);
        const unsigned int u2 = __float_as_uint(q.z);
        const unsigned int u3 = __float_as_uint(q.w);
        // raw-bit compare is exact: noise in [0,1), all positive floats
        cnt += ((u0 < v0) || (u0 == v0 && (j0 + 0) < i0));
        cnt += ((u1 < v0) || (u1 == v0 && (j0 + 1) < i0));
        cnt += ((u2 < v0) || (u2 == v0 && (j0 + 2) < i0));
        cnt += ((u3 < v0) || (u3 == v0 && (j0 + 3) < i0));
        cnt += (((u0 < v1) || (u0 == v1 && (j0 + 0) < i1))) << 16;
        cnt += (((u1 < v1) || (u1 == v1 && (j0 + 1) < i1))) << 16;
        cnt += (((u2 < v1) || (u2 == v1 && (j0 + 2) < i1))) << 16;
        cnt += (((u3 < v1) || (u3 == v1 && (j0 + 3) < i1))) << 16;
    }
#pragma unroll
    for (int o = 16; o > 0; o >>= 1)
        cnt += __shfl_xor_sync(0xFFFFFFFFu, cnt, o);
    if (lane == 0) wred[wid] = cnt;
    __syncthreads();
    int packed = 0;
#pragma unroll
    for (int k = 0; k < 16; k++) packed += wred[k];
    const bool kept0 = (packed & 0xFFFF) < LEN_KEEP;
    const bool kept1 = ((unsigned)packed >> 16) < LEN_KEEP;

    // ---- per-thread segment geometry (same for both windows) ----
    const int seg   = tid >> 3;        // 0..63 window segment
    const int lane8 = tid & 7;
    const int dh = seg >> 3;
    const int dw = seg & 7;

#pragma unroll
    for (int wsel = 0; wsel < 2; wsel++) {
        const int i     = wsel ? i1 : i0;
        const bool kept = wsel ? kept1 : kept0;

        const int wd3 = i % NWH;
        const int r2  = i / NWH;
        const int ww3 = r2 % NWH;
        const int wh3 = r2 / NWH;
        const int h = wh3 * 8 + dh;
        const int w = ww3 * 8 + dw;
        // float4 base of this segment (8 voxels along d, 32 ch = 64 float4)
        const int s0 = (((b * H_ + h) * W_ + w) * D_ + wd3 * 8) * 8 + lane8;

        if (is_xm) {
            if (kept) {
                float4 v[8];
#pragma unroll
                for (int k = 0; k < 8; k++)
                    v[k] = __ldcs(&x[s0 + k * 8]);
#pragma unroll
                for (int k = 0; k < 8; k++)
                    __stcs(&out_xm[s0 + k * 8], v[k]);
            } else {
                const float4 z = make_float4(0.f, 0.f, 0.f, 0.f);
#pragma unroll
                for (int k = 0; k < 8; k++)
                    __stcs(&out_xm[s0 + k * 8], z);
            }
        } else {
            const float fv = kept ? 0.0f : 1.0f;
            const float4 c = make_float4(fv, fv, fv, fv);
#pragma unroll
            for (int k = 0; k < 8; k++)
                __stcs(&out_mk[s0 + k * 8], c);
        }
    }
}

extern "C" void kernel_launch(void* const* d_in, const int* in_sizes, int n_in,
                              void* d_out, int out_size) {
    const float* x     = (const float*)d_in[0];   // [B,H,W,D,C] fp32
    const float* noise = (const float*)d_in[1];   // [B, 1728]   fp32
    float* out = (float*)d_out;                   // [x_masked | mask]

    fused_kernel<<<TOTAL_BLOCKS, 512>>>(
        (const float4*)x,
        (float4*)out,
        (float4*)(out + (long long)ELEMS_PER_OUT),
        noise);
}